// round 15
// baseline (speedup 1.0000x reference)
#include <cuda_runtime.h>
#include <cuda_bf16.h>
#include <math.h>
#include <stdint.h>

#define BN   4
#define CC   256
#define NN   4096
#define DD   32
#define INCH 512

#define MT     128   // query rows per CTA (attn)
#define NT     64    // keys per tile
#define NTILES (NN / NT)

// attn dynamic smem: two (ks,vs) buffers + epilogue overlay
#define KS_SZ   9216                // ks fp32 [32][72]
#define VS_SZ   36864               // vs bf16 [256] rows of 144B
#define BUF_SZ  (KS_SZ + VS_SZ)     // 46080; x2 = 92160
#define SMEM_ATT 135168             // obuf overlay [256][132] fp32 dominates

__device__ float g_q[BN * DD * NN];
__device__ float g_k[BN * DD * NN];
__device__ __nv_bfloat16 g_vb[(size_t)BN * CC * NN];  // [b][c][n] channel-major
__device__ __nv_bfloat16 g_wvb[CC * INCH];            // bf16 V weights

// ---- mma / ldmatrix / cp.async wrappers -----------------------------------
__device__ __forceinline__ void mma_tf32(float* d, const uint32_t* a,
                                         uint32_t b0, uint32_t b1) {
    asm volatile(
        "mma.sync.aligned.m16n8k8.row.col.f32.tf32.tf32.f32 "
        "{%0,%1,%2,%3}, {%4,%5,%6,%7}, {%8,%9}, {%0,%1,%2,%3};"
        : "+f"(d[0]), "+f"(d[1]), "+f"(d[2]), "+f"(d[3])
        : "r"(a[0]), "r"(a[1]), "r"(a[2]), "r"(a[3]), "r"(b0), "r"(b1));
}
__device__ __forceinline__ void mma_bf16(float* d, const uint32_t* a,
                                         uint32_t b0, uint32_t b1) {
    asm volatile(
        "mma.sync.aligned.m16n8k16.row.col.f32.bf16.bf16.f32 "
        "{%0,%1,%2,%3}, {%4,%5,%6,%7}, {%8,%9}, {%0,%1,%2,%3};"
        : "+f"(d[0]), "+f"(d[1]), "+f"(d[2]), "+f"(d[3])
        : "r"(a[0]), "r"(a[1]), "r"(a[2]), "r"(a[3]), "r"(b0), "r"(b1));
}
__device__ __forceinline__ void ldsm_x4(uint32_t& r0, uint32_t& r1,
                                        uint32_t& r2, uint32_t& r3,
                                        uint32_t addr) {
    asm volatile("ldmatrix.sync.aligned.m8n8.x4.shared.b16 {%0,%1,%2,%3}, [%4];"
                 : "=r"(r0), "=r"(r1), "=r"(r2), "=r"(r3) : "r"(addr));
}
__device__ __forceinline__ void ldsm_x4t(uint32_t& r0, uint32_t& r1,
                                         uint32_t& r2, uint32_t& r3,
                                         uint32_t addr) {
    asm volatile("ldmatrix.sync.aligned.m8n8.x4.trans.shared.b16 {%0,%1,%2,%3}, [%4];"
                 : "=r"(r0), "=r"(r1), "=r"(r2), "=r"(r3) : "r"(addr));
}
__device__ __forceinline__ uint32_t smem_u32(const void* p) {
    uint32_t a;
    asm("{ .reg .u64 t; cvta.to.shared.u64 t, %1; cvt.u32.u64 %0, t; }"
        : "=r"(a) : "l"(p));
    return a;
}
__device__ __forceinline__ uint32_t pkbf(float a, float b) {
    __nv_bfloat162 h = __floats2bfloat162_rn(a, b);
    return *(uint32_t*)&h;
}
__device__ __forceinline__ void cpa16(uint32_t dst, const void* src) {
    asm volatile("cp.async.cg.shared.global [%0], [%1], 16;"
                 :: "r"(dst), "l"(src));
}

// ---------------------------------------------------------------------------
// Q/K projection via tf32 HMMA. O=32 out-ch, CTA = 128 px.
// ---------------------------------------------------------------------------
__global__ __launch_bounds__(256) void projQK_kernel(
    const float* __restrict__ x1, const float* __restrict__ x2,
    int C1, int Ctot,
    const float* __restrict__ W, const float* __restrict__ bias,
    float* __restrict__ out)
{
    __shared__ __align__(16) float xs[16 * 136];
    const int m0 = blockIdx.x * 128;
    const int b  = blockIdx.z;
    const int t  = threadIdx.x;
    const int w  = t >> 5, lane = t & 31;
    const int lr = lane >> 2, lc = lane & 3;
    const int wo = w >> 2, wn = w & 3;

    float acc[4][4];
#pragma unroll
    for (int i = 0; i < 4; i++)
#pragma unroll
        for (int j = 0; j < 4; j++) acc[i][j] = 0.f;

    for (int c0 = 0; c0 < Ctot; c0 += 16) {
#pragma unroll
        for (int i = 0; i < 2; i++) {
            int idx = i * 256 + t;
            int r = idx >> 5, c4 = idx & 31;
            int c = c0 + r;
            const float* src = (c < C1)
                ? x1 + ((size_t)b * C1 + c) * NN
                : x2 + ((size_t)b * (Ctot - C1) + (c - C1)) * NN;
            *(float4*)&xs[r * 136 + c4 * 4] = *(const float4*)&src[m0 + c4 * 4];
        }
        __syncthreads();
#pragma unroll
        for (int k8 = 0; k8 < 2; k8++) {
            const float* wr = W + (size_t)(wo * 16 + lr) * Ctot + c0 + k8 * 8;
            uint32_t a[4];
            a[0] = __float_as_uint(wr[lc]);
            a[1] = __float_as_uint(wr[8 * Ctot + lc]);
            a[2] = __float_as_uint(wr[lc + 4]);
            a[3] = __float_as_uint(wr[8 * Ctot + lc + 4]);
#pragma unroll
            for (int nt = 0; nt < 4; nt++) {
                int n = wn * 32 + nt * 8 + lr;
                uint32_t b0 = __float_as_uint(xs[(k8 * 8 + lc) * 136 + n]);
                uint32_t b1 = __float_as_uint(xs[(k8 * 8 + lc + 4) * 136 + n]);
                mma_tf32(acc[nt], a, b0, b1);
            }
        }
        __syncthreads();
    }
    const int o = wo * 16 + lr;
    float bo0 = bias[o], bo1 = bias[o + 8];
#pragma unroll
    for (int nt = 0; nt < 4; nt++) {
        int m = m0 + wn * 32 + nt * 8 + 2 * lc;
        *(float2*)&out[((size_t)(b * 32 + o)) * NN + m] =
            make_float2(acc[nt][0] + bo0, acc[nt][1] + bo0);
        *(float2*)&out[((size_t)(b * 32 + o + 8)) * NN + m] =
            make_float2(acc[nt][2] + bo1, acc[nt][3] + bo1);
    }
}

// ---------------------------------------------------------------------------
// convert V weights fp32 -> bf16 (once)
// ---------------------------------------------------------------------------
__global__ void wconv_kernel(const float* __restrict__ W) {
    int i = (blockIdx.x * 256 + threadIdx.x) * 4;
    float4 v = *(const float4*)&W[i];
    uint2 o = make_uint2(pkbf(v.x, v.y), pkbf(v.z, v.w));
    *(uint2*)&g_wvb[i] = o;
}

// ---------------------------------------------------------------------------
// V projection via bf16 HMMA, register-staged double-buffered k32 chunks.
// CTA = 128 px x 64 out-ch; 8 warps = 4 o16-tiles x 2 m64-halves.
// grid (NN/128, CC/64, BN).
// ---------------------------------------------------------------------------
__global__ __launch_bounds__(256) void projV_kernel(
    const float* __restrict__ x1, const float* __restrict__ x2,
    const float* __restrict__ bias)
{
    __shared__ __align__(16) char xs[2][32 * 272];  // [k32][m128] bf16, 272B rows
    const int m0 = blockIdx.x * 128;
    const int o0 = blockIdx.y * 64;                 // 64 channels per CTA
    const int b  = blockIdx.z;
    const int t  = threadIdx.x;
    const int w  = t >> 5, lane = t & 31;
    const int lr = lane >> 2, lc = lane & 3;
    const int wo = w >> 1, wmh = w & 1;             // 4 o16-tiles x 2 m-halves
    const uint32_t xsb = smem_u32(xs);

    float acc[8][4];
#pragma unroll
    for (int i = 0; i < 8; i++)
#pragma unroll
        for (int j = 0; j < 4; j++) acc[i][j] = 0.f;

    float4 stage[4];
    auto ldc = [&](int c0) {
#pragma unroll
        for (int i = 0; i < 4; i++) {
            int fi = i * 256 + t;
            int kr = fi >> 5, c4 = fi & 31;
            int ci = c0 + kr;
            const float* src = (ci < CC)
                ? x1 + ((size_t)b * CC + ci) * NN
                : x2 + ((size_t)b * CC + (ci - CC)) * NN;
            stage[i] = *(const float4*)&src[m0 + c4 * 4];
        }
    };
    auto stc = [&](int buf) {
#pragma unroll
        for (int i = 0; i < 4; i++) {
            int fi = i * 256 + t;
            int kr = fi >> 5, c4 = fi & 31;
            *(uint2*)(xs[buf] + kr * 272 + c4 * 8) =
                make_uint2(pkbf(stage[i].x, stage[i].y),
                           pkbf(stage[i].z, stage[i].w));
        }
    };

    ldc(0); stc(0);
    __syncthreads();

    for (int c0 = 0; c0 < INCH; c0 += 32) {
        const int cur = (c0 >> 5) & 1;
        const bool more = (c0 + 32 < INCH);
        if (more) ldc(c0 + 32);          // LDG in flight under the mma below

#pragma unroll
        for (int kstep = 0; kstep < 2; kstep++) {
            const __nv_bfloat16* wr =
                g_wvb + (size_t)(o0 + wo * 16 + lr) * INCH + c0 + kstep * 16;
            uint32_t a[4];
            a[0] = *(const uint32_t*)(wr + 2 * lc);
            a[1] = *(const uint32_t*)(wr + 8 * INCH + 2 * lc);
            a[2] = *(const uint32_t*)(wr + 2 * lc + 8);
            a[3] = *(const uint32_t*)(wr + 8 * INCH + 2 * lc + 8);
#pragma unroll
            for (int ntp = 0; ntp < 4; ntp++) {
                uint32_t r0, r1, r2, r3;
                uint32_t addr = xsb + cur * (32 * 272)
                    + (kstep * 16 + (lane & 7) + ((lane >> 3) & 1) * 8) * 272
                    + (wmh * 64 + (ntp * 2 + (lane >> 4)) * 8) * 2;
                ldsm_x4t(r0, r1, r2, r3, addr);
                mma_bf16(acc[ntp * 2],     a, r0, r1);
                mma_bf16(acc[ntp * 2 + 1], a, r2, r3);
            }
        }
        if (more) stc(cur ^ 1);          // buffer cur^1 last read before prior sync
        __syncthreads();
    }

    const int o = o0 + wo * 16 + lr;
    float b0 = bias[o], b1 = bias[o + 8];
#pragma unroll
    for (int nt = 0; nt < 8; nt++) {
        int m = m0 + wmh * 64 + nt * 8 + 2 * lc;
        size_t gi = ((size_t)(b * CC + o)) * NN + m;
        *(uint32_t*)&g_vb[gi] = pkbf(acc[nt][0] + b0, acc[nt][1] + b0);
        *(uint32_t*)&g_vb[gi + 8 * NN] = pkbf(acc[nt][2] + b1, acc[nt][3] + b1);
    }
}

// ---------------------------------------------------------------------------
// Attention FA2: tf32 S (no dup), exp in regs, P reg-chained into bf16 PV.
// K/V tiles double-buffered via cp.async. CTA = 128 rows, 8 warps.
// ---------------------------------------------------------------------------
__global__ __launch_bounds__(256, 1) void attn_kernel(
    const float* __restrict__ ef, const float* __restrict__ gamma_p,
    float* __restrict__ out)
{
    extern __shared__ __align__(16) char smem[];
    const uint32_t sbase = smem_u32(smem);
    float* qs = (float*)smem;              // [k32][m128] stride 132 (pre-loop)
    float* obuf = (float*)smem;            // epilogue overlay [c][m] stride 132
    __shared__ float gri[128];

    const int t = threadIdx.x;
    const int w = t >> 5, lane = t & 31;
    const int lr = lane >> 2, lc = lane & 3;
    const int b  = blockIdx.y;
    const int m0 = blockIdx.x * MT;

    // stage q [32][128], extract resident tf32 A-frags
#pragma unroll
    for (int i = 0; i < 4; i++) {
        int idx = i * 256 + t;
        int d = idx >> 5, mq = idx & 31;
        *(float4*)&qs[d * 132 + mq * 4] =
            *(const float4*)&g_q[((size_t)(b * DD + d)) * NN + m0 + mq * 4];
    }
    __syncthreads();
    uint32_t qf[4][4];
    {
        const int m = w * 16 + lr;
#pragma unroll
        for (int k4 = 0; k4 < 4; k4++) {
            qf[k4][0] = __float_as_uint(qs[(k4 * 8 + lc) * 132 + m]);
            qf[k4][1] = __float_as_uint(qs[(k4 * 8 + lc) * 132 + m + 8]);
            qf[k4][2] = __float_as_uint(qs[(k4 * 8 + lc + 4) * 132 + m]);
            qf[k4][3] = __float_as_uint(qs[(k4 * 8 + lc + 4) * 132 + m + 8]);
        }
    }
    __syncthreads();

    float acc[32][4];
#pragma unroll
    for (int i = 0; i < 32; i++)
#pragma unroll
        for (int j = 0; j < 4; j++) acc[i][j] = 0.f;
    float psum_lo = 0.f, psum_hi = 0.f;

    // ---- prefetch tile 0 into buffer 0
    {
        const int n0 = 0;
        uint32_t ksb = sbase, vsb2 = sbase + KS_SZ;
#pragma unroll
        for (int i = 0; i < 2; i++) {
            int idx = i * 256 + t;
            int d = idx >> 4, nq = idx & 15;
            cpa16(ksb + d * 288 + nq * 16,
                  &g_k[((size_t)(b * DD + d)) * NN + n0 + nq * 4]);
        }
#pragma unroll
        for (int it = 0; it < 8; it++) {
            int idx = it * 256 + t;
            int c = idx >> 3, seg = idx & 7;
            cpa16(vsb2 + c * 144 + seg * 16,
                  &g_vb[((size_t)(b * CC + c)) * NN + n0 + seg * 8]);
        }
        asm volatile("cp.async.commit_group;" ::: "memory");
    }

    for (int ti = 0; ti < NTILES; ti++) {
        const int cur = ti & 1;
        if (ti + 1 < NTILES) {
            const int n0 = (ti + 1) * NT;
            uint32_t ksb = sbase + (cur ^ 1) * BUF_SZ;
            uint32_t vsb2 = ksb + KS_SZ;
#pragma unroll
            for (int i = 0; i < 2; i++) {
                int idx = i * 256 + t;
                int d = idx >> 4, nq = idx & 15;
                cpa16(ksb + d * 288 + nq * 16,
                      &g_k[((size_t)(b * DD + d)) * NN + n0 + nq * 4]);
            }
#pragma unroll
            for (int it = 0; it < 8; it++) {
                int idx = it * 256 + t;
                int c = idx >> 3, seg = idx & 7;
                cpa16(vsb2 + c * 144 + seg * 16,
                      &g_vb[((size_t)(b * CC + c)) * NN + n0 + seg * 8]);
            }
            asm volatile("cp.async.commit_group;" ::: "memory");
            asm volatile("cp.async.wait_group 1;" ::: "memory");
        } else {
            asm volatile("cp.async.wait_group 0;" ::: "memory");
        }
        __syncthreads();

        const float* ks = (const float*)(smem + cur * BUF_SZ);
        const uint32_t vsb = sbase + cur * BUF_SZ + KS_SZ;

        // ---- S: m16 x n64 tf32 (once per row)
        float sacc[8][4];
#pragma unroll
        for (int l = 0; l < 8; l++)
#pragma unroll
            for (int j = 0; j < 4; j++) sacc[l][j] = 0.f;
#pragma unroll
        for (int k4 = 0; k4 < 4; k4++) {
            const int kr = k4 * 8;
#pragma unroll
            for (int nt = 0; nt < 8; nt++) {
                int n = nt * 8 + lr;
                uint32_t b0 = __float_as_uint(ks[(kr + lc) * 72 + n]);
                uint32_t b1 = __float_as_uint(ks[(kr + lc + 4) * 72 + n]);
                mma_tf32(sacc[nt], qf[k4], b0, b1);
            }
        }
        // ---- exp (bounded, no max-sub) + psum + pack PV A-frags
        uint32_t pv_a[4][4];
#pragma unroll
        for (int kt = 0; kt < 4; kt++) {
            float e00 = __expf(sacc[2 * kt][0]), e01 = __expf(sacc[2 * kt][1]);
            float e02 = __expf(sacc[2 * kt][2]), e03 = __expf(sacc[2 * kt][3]);
            float e10 = __expf(sacc[2 * kt + 1][0]), e11 = __expf(sacc[2 * kt + 1][1]);
            float e12 = __expf(sacc[2 * kt + 1][2]), e13 = __expf(sacc[2 * kt + 1][3]);
            psum_lo += (e00 + e01) + (e10 + e11);
            psum_hi += (e02 + e03) + (e12 + e13);
            pv_a[kt][0] = pkbf(e00, e01);
            pv_a[kt][1] = pkbf(e02, e03);
            pv_a[kt][2] = pkbf(e10, e11);
            pv_a[kt][3] = pkbf(e12, e13);
        }

        // ---- PV: acc[m16, c256] += P[m16,k64] x V[c256,k64]^T
#pragma unroll
        for (int ntc = 0; ntc < 32; ntc++) {
            uint32_t base = vsb + (ntc * 8 + (lane & 7)) * 144 + ((lane >> 3) * 16);
            uint32_t v0, v1, v2, v3;
            ldsm_x4(v0, v1, v2, v3, base);
            mma_bf16(acc[ntc], pv_a[0], v0, v1);
            mma_bf16(acc[ntc], pv_a[1], v2, v3);
            ldsm_x4(v0, v1, v2, v3, base + 64);
            mma_bf16(acc[ntc], pv_a[2], v0, v1);
            mma_bf16(acc[ntc], pv_a[3], v2, v3);
        }
        __syncthreads();
    }

    // ---- row sums -> gri = gamma / psum
    psum_lo += __shfl_xor_sync(0xffffffffu, psum_lo, 1);
    psum_lo += __shfl_xor_sync(0xffffffffu, psum_lo, 2);
    psum_hi += __shfl_xor_sync(0xffffffffu, psum_hi, 1);
    psum_hi += __shfl_xor_sync(0xffffffffu, psum_hi, 2);
    float gamma = gamma_p[0];
    if (lc == 0) {
        gri[w * 16 + lr]     = gamma / psum_lo;
        gri[w * 16 + lr + 8] = gamma / psum_hi;
    }
    __syncthreads();   // tiles dead; obuf overlay begins

    // ---- stage acc into obuf[c][m] (stride 132)
#pragma unroll
    for (int ntc = 0; ntc < 32; ntc++) {
        int c = ntc * 8 + 2 * lc;
        int m = w * 16 + lr;
        obuf[c * 132 + m]           = acc[ntc][0];
        obuf[(c + 1) * 132 + m]     = acc[ntc][1];
        obuf[c * 132 + m + 8]       = acc[ntc][2];
        obuf[(c + 1) * 132 + m + 8] = acc[ntc][3];
    }
    __syncthreads();

    // ---- final: out = obuf * gri + ef, coalesced float4
#pragma unroll
    for (int i = 0; i < 32; i++) {
        int idx = i * 256 + t;
        int c = idx >> 5, mq = idx & 31;
        size_t gi = ((size_t)(b * CC + c)) * NN + m0 + mq * 4;
        float4 e4 = *(const float4*)&ef[gi];
        float4 o4;
        o4.x = obuf[c * 132 + mq * 4 + 0] * gri[mq * 4 + 0] + e4.x;
        o4.y = obuf[c * 132 + mq * 4 + 1] * gri[mq * 4 + 1] + e4.y;
        o4.z = obuf[c * 132 + mq * 4 + 2] * gri[mq * 4 + 2] + e4.z;
        o4.w = obuf[c * 132 + mq * 4 + 3] * gri[mq * 4 + 3] + e4.w;
        *(float4*)&out[gi] = o4;
    }
}

// ---------------------------------------------------------------------------
extern "C" void kernel_launch(void* const* d_in, const int* in_sizes, int n_in,
                              void* d_out, int out_size)
{
    const float* ef = (const float*)d_in[0];
    const float* sf = (const float*)d_in[1];
    const float* At = (const float*)d_in[2];
    const float* Qw = (const float*)d_in[3];
    const float* Qb = (const float*)d_in[4];
    const float* Kw = (const float*)d_in[5];
    const float* Kb = (const float*)d_in[6];
    const float* Vw = (const float*)d_in[7];
    const float* Vb = (const float*)d_in[8];
    const float* gm = (const float*)d_in[9];
    float* out = (float*)d_out;

    float *qp, *kp;
    cudaGetSymbolAddress((void**)&qp, g_q);
    cudaGetSymbolAddress((void**)&kp, g_k);

    cudaFuncSetAttribute(attn_kernel,
                         cudaFuncAttributeMaxDynamicSharedMemorySize, SMEM_ATT);

    wconv_kernel<<<CC * INCH / 1024, 256>>>(Vw);
    projQK_kernel<<<dim3(NN / 128, 1, BN), 256>>>(ef, sf, CC, INCH, Qw, Qb, qp);
    projQK_kernel<<<dim3(NN / 128, 1, BN), 256>>>(At, At, CC, CC, Kw, Kb, kp);
    projV_kernel<<<dim3(NN / 128, CC / 64, BN), 256>>>(ef, sf, Vb);

    attn_kernel<<<dim3(NN / MT, BN), 256, SMEM_ATT>>>(ef, gm, out);
}